// round 1
// baseline (speedup 1.0000x reference)
#include <cuda_runtime.h>

#define EPS 1e-5f
#define V_DIM 32
#define D_DIM 128

// Per-variable statistics: [v*8 + {Wbar, bbar, varW, cov, varb, pad...}]
__device__ float g_stats[V_DIM * 8];

// ---------------------------------------------------------------------------
// Prologue: compute per-v stats of W[v,:], b[v,:]. One warp per v.
// ---------------------------------------------------------------------------
__global__ void stats_kernel(const float* __restrict__ W,
                             const float* __restrict__ b) {
    int v    = blockIdx.x;       // 0..31
    int lane = threadIdx.x;      // 0..31

    const float4* W4 = reinterpret_cast<const float4*>(W + v * D_DIM);
    const float4* b4 = reinterpret_cast<const float4*>(b + v * D_DIM);
    float4 w = W4[lane];
    float4 bb = b4[lane];

    float sw = w.x + w.y + w.z + w.w;
    float sb = bb.x + bb.y + bb.z + bb.w;
    #pragma unroll
    for (int off = 16; off > 0; off >>= 1) {
        sw += __shfl_xor_sync(0xFFFFFFFFu, sw, off);
        sb += __shfl_xor_sync(0xFFFFFFFFu, sb, off);
    }
    float Wbar = sw * (1.0f / D_DIM);
    float bbar = sb * (1.0f / D_DIM);

    float wc0 = w.x - Wbar, wc1 = w.y - Wbar, wc2 = w.z - Wbar, wc3 = w.w - Wbar;
    float bc0 = bb.x - bbar, bc1 = bb.y - bbar, bc2 = bb.z - bbar, bc3 = bb.w - bbar;

    float sww = wc0*wc0 + wc1*wc1 + wc2*wc2 + wc3*wc3;
    float swb = wc0*bc0 + wc1*bc1 + wc2*bc2 + wc3*bc3;
    float sbb = bc0*bc0 + bc1*bc1 + bc2*bc2 + bc3*bc3;
    #pragma unroll
    for (int off = 16; off > 0; off >>= 1) {
        sww += __shfl_xor_sync(0xFFFFFFFFu, sww, off);
        swb += __shfl_xor_sync(0xFFFFFFFFu, swb, off);
        sbb += __shfl_xor_sync(0xFFFFFFFFu, sbb, off);
    }
    if (lane == 0) {
        g_stats[v * 8 + 0] = Wbar;
        g_stats[v * 8 + 1] = bbar;
        g_stats[v * 8 + 2] = sww * (1.0f / D_DIM);  // Var(W)
        g_stats[v * 8 + 3] = swb * (1.0f / D_DIM);  // Cov(W,b)
        g_stats[v * 8 + 4] = sbb * (1.0f / D_DIM);  // Var(b)
    }
}

// ---------------------------------------------------------------------------
// Main elementwise kernel: one thread per output float4.
//   row = (b*S + s)*V + v ; v = row & 31 ; warp == one D=128 row.
// out = relu(gamma * (h - mu) * rs + beta), h = x*W + b,
// with mu, rs computed analytically from per-v stats (no reduction).
// ---------------------------------------------------------------------------
__global__ void __launch_bounds__(256)
ve_kernel(const float* __restrict__ x,
          const float* __restrict__ W,
          const float* __restrict__ b,
          const float* __restrict__ gamma,
          const float* __restrict__ beta,
          float* __restrict__ out,
          int n4) {
    int i4 = blockIdx.x * blockDim.x + threadIdx.x;
    if (i4 >= n4) return;

    int row = i4 >> 5;          // D/4 = 32 float4s per row
    int d4  = i4 & 31;
    int v   = row & (V_DIM - 1);

    float xv = __ldg(&x[row]);

    float Wbar = g_stats[v * 8 + 0];
    float bbar = g_stats[v * 8 + 1];
    float varW = g_stats[v * 8 + 2];
    float cov  = g_stats[v * 8 + 3];
    float varb = g_stats[v * 8 + 4];

    // var(h) = x^2*varW + 2x*cov + varb
    float var = fmaf(xv, fmaf(xv, varW, 2.0f * cov), varb);
    float rs  = rsqrtf(var + EPS);
    float mu  = fmaf(xv, Wbar, bbar);
    float nmr = -mu * rs;       // so (h - mu)*rs = fma(h, rs, nmr)

    int t = v * 32 + d4;        // index into [V, D/4] tables
    float4 w4 = __ldg(reinterpret_cast<const float4*>(W)     + t);
    float4 b4 = __ldg(reinterpret_cast<const float4*>(b)     + t);
    float4 g4 = __ldg(reinterpret_cast<const float4*>(gamma) + t);
    float4 e4 = __ldg(reinterpret_cast<const float4*>(beta)  + t);

    float4 o;
    {
        float h = fmaf(w4.x, xv, b4.x);
        float y = fmaf(h, rs, nmr);
        o.x = fmaxf(fmaf(g4.x, y, e4.x), 0.0f);
    }
    {
        float h = fmaf(w4.y, xv, b4.y);
        float y = fmaf(h, rs, nmr);
        o.y = fmaxf(fmaf(g4.y, y, e4.y), 0.0f);
    }
    {
        float h = fmaf(w4.z, xv, b4.z);
        float y = fmaf(h, rs, nmr);
        o.z = fmaxf(fmaf(g4.z, y, e4.z), 0.0f);
    }
    {
        float h = fmaf(w4.w, xv, b4.w);
        float y = fmaf(h, rs, nmr);
        o.w = fmaxf(fmaf(g4.w, y, e4.w), 0.0f);
    }
    reinterpret_cast<float4*>(out)[i4] = o;
}

// ---------------------------------------------------------------------------
extern "C" void kernel_launch(void* const* d_in, const int* in_sizes, int n_in,
                              void* d_out, int out_size) {
    const float* x     = (const float*)d_in[0];
    const float* W     = (const float*)d_in[1];
    const float* b     = (const float*)d_in[2];
    const float* gamma = (const float*)d_in[3];
    const float* beta  = (const float*)d_in[4];
    float* out = (float*)d_out;

    // out_size = B*S*V*D = 134217728 ; n4 = out_size/4
    int n4 = out_size / 4;

    stats_kernel<<<V_DIM, 32>>>(W, b);

    int threads = 256;
    int blocks  = (n4 + threads - 1) / threads;
    ve_kernel<<<blocks, threads>>>(x, W, b, gamma, beta, out, n4);
}

// round 2
// speedup vs baseline: 1.1324x; 1.1324x over previous
#include <cuda_runtime.h>

#define EPS   1e-5f
#define V_DIM 32
#define D_DIM 128
#define ITERS 64   // rows per warp

// ---------------------------------------------------------------------------
// One warp owns a fixed v. Lanes hold the 128-wide tables in registers
// (float4 per lane). Warp computes per-v stats once via shuffles, then
// streams ITERS rows: per row = 1 uniform x load + FMAs + 1 STG.128.
//
// Analytic LayerNorm (no per-row reduction):
//   h  = x*W + b
//   mu = x*Wbar + bbar
//   var= x^2*Var(W) + 2x*Cov(W,b) + Var(b)
// ---------------------------------------------------------------------------
__global__ void __launch_bounds__(256)
ve_kernel(const float* __restrict__ x,
          const float* __restrict__ W,
          const float* __restrict__ b,
          const float* __restrict__ gamma,
          const float* __restrict__ beta,
          float* __restrict__ out) {
    int gwarp = (blockIdx.x * blockDim.x + threadIdx.x) >> 5;
    int lane  = threadIdx.x & 31;
    int v     = gwarp & (V_DIM - 1);
    int group = gwarp >> 5;          // which chunk of rows for this v

    int t = v * 32 + lane;           // index into [V, D/4] tables
    float4 w4 = __ldg(reinterpret_cast<const float4*>(W)     + t);
    float4 b4 = __ldg(reinterpret_cast<const float4*>(b)     + t);
    float4 g4 = __ldg(reinterpret_cast<const float4*>(gamma) + t);
    float4 e4 = __ldg(reinterpret_cast<const float4*>(beta)  + t);

    // ---- per-v stats via butterfly reductions (all lanes get results) ----
    float sw = w4.x + w4.y + w4.z + w4.w;
    float sb = b4.x + b4.y + b4.z + b4.w;
    #pragma unroll
    for (int off = 16; off > 0; off >>= 1) {
        sw += __shfl_xor_sync(0xFFFFFFFFu, sw, off);
        sb += __shfl_xor_sync(0xFFFFFFFFu, sb, off);
    }
    float Wbar = sw * (1.0f / D_DIM);
    float bbar = sb * (1.0f / D_DIM);

    float wc0 = w4.x - Wbar, wc1 = w4.y - Wbar, wc2 = w4.z - Wbar, wc3 = w4.w - Wbar;
    float bc0 = b4.x - bbar, bc1 = b4.y - bbar, bc2 = b4.z - bbar, bc3 = b4.w - bbar;
    float sww = wc0*wc0 + wc1*wc1 + wc2*wc2 + wc3*wc3;
    float swb = wc0*bc0 + wc1*bc1 + wc2*bc2 + wc3*bc3;
    float sbb = bc0*bc0 + bc1*bc1 + bc2*bc2 + bc3*bc3;
    #pragma unroll
    for (int off = 16; off > 0; off >>= 1) {
        sww += __shfl_xor_sync(0xFFFFFFFFu, sww, off);
        swb += __shfl_xor_sync(0xFFFFFFFFu, swb, off);
        sbb += __shfl_xor_sync(0xFFFFFFFFu, sbb, off);
    }
    float varW = sww * (1.0f / D_DIM);
    float cov2 = swb * (2.0f / D_DIM);   // 2*Cov(W,b)
    float varb = sbb * (1.0f / D_DIM);

    // ---- mainloop: stream rows n = group*ITERS .. +ITERS-1 for this v ----
    const float* xp = x + v;             // x[n*V + v]
    float4* out4 = reinterpret_cast<float4*>(out);
    int n0 = group * ITERS;

    #pragma unroll 4
    for (int i = 0; i < ITERS; i++) {
        int n = n0 + i;
        float xv = __ldg(xp + n * V_DIM);

        float var = fmaf(xv, fmaf(xv, varW, cov2), varb);
        float rs  = rsqrtf(var + EPS);
        float mu  = fmaf(xv, Wbar, bbar);
        float nmr = -mu * rs;            // (h-mu)*rs == fma(h, rs, nmr)

        float4 o;
        {
            float h = fmaf(w4.x, xv, b4.x);
            float y = fmaf(h, rs, nmr);
            o.x = fmaxf(fmaf(g4.x, y, e4.x), 0.0f);
        }
        {
            float h = fmaf(w4.y, xv, b4.y);
            float y = fmaf(h, rs, nmr);
            o.y = fmaxf(fmaf(g4.y, y, e4.y), 0.0f);
        }
        {
            float h = fmaf(w4.z, xv, b4.z);
            float y = fmaf(h, rs, nmr);
            o.z = fmaxf(fmaf(g4.z, y, e4.z), 0.0f);
        }
        {
            float h = fmaf(w4.w, xv, b4.w);
            float y = fmaf(h, rs, nmr);
            o.w = fmaxf(fmaf(g4.w, y, e4.w), 0.0f);
        }
        out4[(n * V_DIM + v) * 32 + lane] = o;
    }
}

// ---------------------------------------------------------------------------
extern "C" void kernel_launch(void* const* d_in, const int* in_sizes, int n_in,
                              void* d_out, int out_size) {
    const float* x     = (const float*)d_in[0];
    const float* W     = (const float*)d_in[1];
    const float* b     = (const float*)d_in[2];
    const float* gamma = (const float*)d_in[3];
    const float* beta  = (const float*)d_in[4];
    float* out = (float*)d_out;

    // total rows = out_size / D ; rows per v = total/V ; warps = V * (per_v/ITERS)
    long long n_rows = (long long)out_size / D_DIM;          // 1,048,576
    long long per_v  = n_rows / V_DIM;                       // 32,768
    long long warps  = (per_v / ITERS) * V_DIM;              // 16,384
    int threads = 256;
    int blocks  = (int)(warps * 32 / threads);               // 2,048

    ve_kernel<<<blocks, threads>>>(x, W, b, gamma, beta, out);
}